// round 11
// baseline (speedup 1.0000x reference)
#include <cuda_runtime.h>
#include <cstdint>

#define EPSV 1e-5f
constexpr int BB = 32, CIN = 240, C1 = 24, HH = 56, WWD = 56, HW = 3136;
constexpr int OUP = 240;
constexpr int KQ = 60;                 // K quarter size

// Scratch — __device__ globals per allocation rules.
__device__ float g_p0[BB * C1 * HW];
__device__ float g_p1[BB * C1 * HW];
__device__ float g_p2[BB * C1 * HW];
__device__ float g_p3[BB * C1 * HW];
__device__ float g_s2[BB * C1 * HW];   // after dw3x3 + bn2 (== x1)
__device__ float* const g_parts[4] = {g_p0, g_p1, g_p2, g_p3};

using u64 = unsigned long long;

__device__ __forceinline__ u64 pk2(float lo, float hi) {
    u64 r; asm("mov.b64 %0, {%1,%2};" : "=l"(r) : "f"(lo), "f"(hi)); return r;
}
__device__ __forceinline__ float2 up2(u64 v) {
    float2 f; asm("mov.b64 {%0,%1}, %2;" : "=f"(f.x), "=f"(f.y) : "l"(v)); return f;
}
__device__ __forceinline__ u64 fma2(u64 a, u64 b, u64 c) {
    u64 d; asm("fma.rn.f32x2 %0, %1, %2, %3;" : "=l"(d) : "l"(a), "l"(b), "l"(c)); return d;
}
__device__ __forceinline__ u64 add2(u64 a, u64 b) {
    u64 d; asm("add.rn.f32x2 %0, %1, %2;" : "=l"(d) : "l"(a), "l"(b)); return d;
}

// ---------------------------------------------------------------------------
// Kernel A: 1x1 conv raw partial sums.
// grid (98 px-tiles, 2 ch-halves, 4 K-quarters), 128 thr = 784 CTAs.
// Thread = 8 px x 12 ch: 48 f32x2 accumulators; per k: 12 LDS.64 broadcasts
// feed 48 FFMA2 (ratio 4 — twice R6) while total threads stay 100352
// (~16-21 warps/SM). x via 2 LDG.128/k, ping-pong depth 2k.
// ---------------------------------------------------------------------------
__global__ __launch_bounds__(128, 4) void kA(
    const float* __restrict__ x, const float* __restrict__ w) {
    __shared__ u64 ws[KQ * 12];            // [k][c] = {w,w} dup pairs, 5.76 KB
    int tid = threadIdx.x;
    int chb = blockIdx.y * 12;             // channel half base
    int kbase = blockIdx.z * KQ;           // K quarter base
    for (int i = tid; i < KQ * 12; i += 128) {
        int k = i / 12, cc = i % 12;
        float wv = w[(chb + cc) * CIN + kbase + k];
        ws[i] = pk2(wv, wv);
    }
    __syncthreads();

    int p0 = (blockIdx.x * 128 + tid) * 8; // 8 contiguous px, HW%8==0
    int b = p0 / HW;
    int s = p0 - b * HW;
    const float* xpf = x + (size_t)b * CIN * HW + (size_t)kbase * HW + s;

    u64 acc[12][4];
#pragma unroll
    for (int c = 0; c < 12; c++)
#pragma unroll
        for (int j = 0; j < 4; j++) acc[c][j] = 0ull;

    ulonglong2 bufA[2], bufB[2];           // 1 k-step each (8 px = 2 u2)
    bufA[0] = *reinterpret_cast<const ulonglong2*>(xpf);
    bufA[1] = *reinterpret_cast<const ulonglong2*>(xpf + 4);
    bufB[0] = *reinterpret_cast<const ulonglong2*>(xpf + HW);
    bufB[1] = *reinterpret_cast<const ulonglong2*>(xpf + HW + 4);

#pragma unroll 1
    for (int k0 = 0; k0 < KQ; k0 += 2) {
        // compute k0 from A
        {
            u64 x0 = bufA[0].x, x1 = bufA[0].y, x2 = bufA[1].x, x3 = bufA[1].y;
            const u64* wk = ws + k0 * 12;
#pragma unroll
            for (int c = 0; c < 12; c++) {
                u64 wv = wk[c];
                acc[c][0] = fma2(x0, wv, acc[c][0]);
                acc[c][1] = fma2(x1, wv, acc[c][1]);
                acc[c][2] = fma2(x2, wv, acc[c][2]);
                acc[c][3] = fma2(x3, wv, acc[c][3]);
            }
        }
        // refill A <- k0+2 (clamped; harmless L1 re-hit on last iter)
        {
            int ka = (k0 + 2 < KQ) ? (k0 + 2) : 0;
            bufA[0] = *reinterpret_cast<const ulonglong2*>(xpf + (size_t)ka * HW);
            bufA[1] = *reinterpret_cast<const ulonglong2*>(xpf + (size_t)ka * HW + 4);
        }
        // compute k0+1 from B
        {
            u64 x0 = bufB[0].x, x1 = bufB[0].y, x2 = bufB[1].x, x3 = bufB[1].y;
            const u64* wk = ws + (k0 + 1) * 12;
#pragma unroll
            for (int c = 0; c < 12; c++) {
                u64 wv = wk[c];
                acc[c][0] = fma2(x0, wv, acc[c][0]);
                acc[c][1] = fma2(x1, wv, acc[c][1]);
                acc[c][2] = fma2(x2, wv, acc[c][2]);
                acc[c][3] = fma2(x3, wv, acc[c][3]);
            }
        }
        // refill B <- k0+3
        {
            int kb2 = (k0 + 3 < KQ) ? (k0 + 3) : 0;
            bufB[0] = *reinterpret_cast<const ulonglong2*>(xpf + (size_t)kb2 * HW);
            bufB[1] = *reinterpret_cast<const ulonglong2*>(xpf + (size_t)kb2 * HW + 4);
        }
    }
    float* op = g_parts[blockIdx.z] + ((size_t)b * C1 + chb) * HW + s;
#pragma unroll
    for (int c = 0; c < 12; c++) {
        float2 f0 = up2(acc[c][0]), f1 = up2(acc[c][1]);
        float2 f2 = up2(acc[c][2]), f3 = up2(acc[c][3]);
        *reinterpret_cast<float4*>(op + (size_t)c * HW) =
            make_float4(f0.x, f0.y, f1.x, f1.y);
        *reinterpret_cast<float4*>(op + (size_t)c * HW + 4) =
            make_float4(f2.x, f2.y, f3.x, f3.y);
    }
}

// ---------------------------------------------------------------------------
// Kernel B: merge 4 partials + BN1, depthwise 3x3 + BN2. One q (4px)/thread.
// Flat grid 2352 x 256. Writes g_s2 (for kC, via L2) and out channels [0,24).
// ---------------------------------------------------------------------------
__global__ __launch_bounds__(256) void kB(
    const float* __restrict__ g1, const float* __restrict__ b1,
    const float* __restrict__ m1, const float* __restrict__ v1,
    const float* __restrict__ wdw,
    const float* __restrict__ g2, const float* __restrict__ b2,
    const float* __restrict__ m2, const float* __restrict__ v2,
    float* __restrict__ out) {
    int idx = blockIdx.x * 256 + threadIdx.x;   // 602112 = 32*24*784
    int q = idx % 784;
    int c = (idx / 784) % C1;
    int b = idx / (784 * C1);
    int h = q / 14;
    int w0 = (q % 14) * 4;
    float iv1 = g1[c] * rsqrtf(v1[c] + EPSV);
    float bi1 = b1[c] - m1[c] * iv1;
    size_t poff = ((size_t)b * C1 + c) * HW;
    const float* p0 = g_p0 + poff;
    const float* p1 = g_p1 + poff;
    const float* p2 = g_p2 + poff;
    const float* p3 = g_p3 + poff;

    float rb[3][6];
#pragma unroll
    for (int dy = 0; dy < 3; dy++) {
        int hh = h + dy - 1;
        bool hok = (hh >= 0) && (hh < HH);
#pragma unroll
        for (int jx = 0; jx < 6; jx++) {
            int ww = w0 + jx - 1;
            int id2 = hh * WWD + ww;
            rb[dy][jx] = (hok && ww >= 0 && ww < WWD)
                ? fmaf((p0[id2] + p1[id2]) + (p2[id2] + p3[id2]), iv1, bi1)
                : 0.0f;
        }
    }
    float wv[9];
#pragma unroll
    for (int t = 0; t < 9; t++) wv[t] = __ldg(wdw + c * 9 + t);
    float acc[4] = {0.f, 0.f, 0.f, 0.f};
#pragma unroll
    for (int dy = 0; dy < 3; dy++)
#pragma unroll
        for (int dx = 0; dx < 3; dx++) {
            float t = wv[dy * 3 + dx];
#pragma unroll
            for (int j = 0; j < 4; j++) acc[j] = fmaf(rb[dy][dx + j], t, acc[j]);
        }
    float iv2 = g2[c] * rsqrtf(v2[c] + EPSV);
    float bi2 = b2[c] - m2[c] * iv2;
    float4 o = make_float4(fmaf(acc[0], iv2, bi2), fmaf(acc[1], iv2, bi2),
                           fmaf(acc[2], iv2, bi2), fmaf(acc[3], iv2, bi2));
    size_t off = poff + h * WWD + w0;
    *reinterpret_cast<float4*>(g_s2 + off) = o;
    size_t ooff = ((size_t)b * OUP + c) * HW + h * WWD + w0;
    *reinterpret_cast<float4*>(out + ooff) = o;
}

// ---------------------------------------------------------------------------
// Kernel C: adder depthwise (24 -> 216) + BN3 + ReLU into out channels [24,240).
// One q (4px) per thread, grid (7, 24, 32) x 128. Reads g_s2 from L2.
// ---------------------------------------------------------------------------
__global__ __launch_bounds__(128) void kC(
    const float* __restrict__ wadd,
    const float* __restrict__ g3, const float* __restrict__ b3,
    const float* __restrict__ m3, const float* __restrict__ v3,
    float* __restrict__ out) {
    int c = blockIdx.y;
    int b = blockIdx.z;
    __shared__ u64 negtap[81];
    __shared__ float sninv[9], sbias[9];
    int tid = threadIdx.x;
    if (tid < 81) {
        float tv = wadd[c * 81 + tid];
        negtap[tid] = pk2(-tv, -tv);
    }
    if (tid < 9) {
        int ch = c * 9 + tid;
        float iv = g3[ch] * rsqrtf(v3[ch] + EPSV);
        sninv[tid] = -iv;
        sbias[tid] = b3[ch] - m3[ch] * iv;
    }
    __syncthreads();
    int q = blockIdx.x * 128 + tid;
    if (q >= 784) return;
    int h = q / 14;
    int w0 = (q % 14) * 4;
    const float* p = g_s2 + ((size_t)b * C1 + c) * HW;

    float rb[3][6];
#pragma unroll
    for (int dy = 0; dy < 3; dy++) {
        int hh = h + dy - 1;
        bool hok = (hh >= 0) && (hh < HH);
#pragma unroll
        for (int jx = 0; jx < 6; jx++) {
            int ww = w0 + jx - 1;
            rb[dy][jx] = (hok && ww >= 0 && ww < WWD) ? p[hh * WWD + ww] : 0.0f;
        }
    }
    u64 nA[9], nB[9];
#pragma unroll
    for (int dy = 0; dy < 3; dy++)
#pragma unroll
        for (int dx = 0; dx < 3; dx++) {
            nA[dy * 3 + dx] = pk2(rb[dy][dx],     rb[dy][dx + 1]);
            nB[dy * 3 + dx] = pk2(rb[dy][dx + 2], rb[dy][dx + 3]);
        }
    size_t obase = ((size_t)b * OUP + C1 + c * 9) * HW + h * WWD + w0;
#pragma unroll
    for (int r = 0; r < 9; r++) {
        u64 aA = 0ull, aB = 0ull;
#pragma unroll
        for (int t = 0; t < 9; t++) {
            u64 nt = negtap[r * 9 + t];
            u64 dA = add2(nA[t], nt) & 0x7FFFFFFF7FFFFFFFull;
            u64 dB = add2(nB[t], nt) & 0x7FFFFFFF7FFFFFFFull;
            aA = add2(aA, dA);
            aB = add2(aB, dB);
        }
        float2 fa = up2(aA), fb = up2(aB);
        float ni = sninv[r], bi = sbias[r];
        float4 o = make_float4(fmaxf(fmaf(fa.x, ni, bi), 0.f),
                               fmaxf(fmaf(fa.y, ni, bi), 0.f),
                               fmaxf(fmaf(fb.x, ni, bi), 0.f),
                               fmaxf(fmaf(fb.y, ni, bi), 0.f));
        *reinterpret_cast<float4*>(out + obase + (size_t)r * HW) = o;
    }
}

extern "C" void kernel_launch(void* const* d_in, const int* in_sizes, int n_in,
                              void* d_out, int out_size) {
    const float* x   = (const float*)d_in[0];
    const float* wp  = (const float*)d_in[1];
    const float* g1  = (const float*)d_in[2];
    const float* b1  = (const float*)d_in[3];
    const float* m1  = (const float*)d_in[4];
    const float* v1  = (const float*)d_in[5];
    const float* wdw = (const float*)d_in[6];
    const float* g2  = (const float*)d_in[7];
    const float* b2  = (const float*)d_in[8];
    const float* m2  = (const float*)d_in[9];
    const float* v2  = (const float*)d_in[10];
    const float* wa  = (const float*)d_in[11];
    const float* g3  = (const float*)d_in[12];
    const float* b3  = (const float*)d_in[13];
    const float* m3  = (const float*)d_in[14];
    const float* v3  = (const float*)d_in[15];
    float* out = (float*)d_out;

    kA<<<dim3(98, 2, 4), 128>>>(x, wp);
    kB<<<2352, 256>>>(g1, b1, m1, v1, wdw, g2, b2, m2, v2, out);
    kC<<<dim3(7, 24, 32), 128>>>(wa, g3, b3, m3, v3, out);
}

// round 12
// speedup vs baseline: 1.1613x; 1.1613x over previous
#include <cuda_runtime.h>
#include <cstdint>

#define EPSV 1e-5f
constexpr int BB = 32, CIN = 240, C1 = 24, HH = 56, WWD = 56, HW = 3136;
constexpr int OUP = 240;
constexpr int KQ = 60;                 // K quarter size

// Scratch — __device__ globals per allocation rules.
__device__ float g_p0[BB * C1 * HW];
__device__ float g_p1[BB * C1 * HW];
__device__ float g_p2[BB * C1 * HW];
__device__ float g_p3[BB * C1 * HW];
__device__ float g_s2[BB * C1 * HW];   // after dw3x3 + bn2 (== x1)
__device__ float* const g_parts[4] = {g_p0, g_p1, g_p2, g_p3};

using u64 = unsigned long long;

__device__ __forceinline__ u64 pk2(float lo, float hi) {
    u64 r; asm("mov.b64 %0, {%1,%2};" : "=l"(r) : "f"(lo), "f"(hi)); return r;
}
__device__ __forceinline__ float2 up2(u64 v) {
    float2 f; asm("mov.b64 {%0,%1}, %2;" : "=f"(f.x), "=f"(f.y) : "l"(v)); return f;
}
__device__ __forceinline__ u64 fma2(u64 a, u64 b, u64 c) {
    u64 d; asm("fma.rn.f32x2 %0, %1, %2, %3;" : "=l"(d) : "l"(a), "l"(b), "l"(c)); return d;
}
__device__ __forceinline__ u64 add2(u64 a, u64 b) {
    u64 d; asm("add.rn.f32x2 %0, %1, %2;" : "=l"(d) : "l"(a), "l"(b)); return d;
}

// ---------------------------------------------------------------------------
// Kernel A: 1x1 conv raw partial sums — R6 dataflow (best measured: 48.2us),
// grid scaled 2x via K-quarters for occupancy.
// grid (196 px-tiles, 2 ch-halves, 4 K-quarters) = 1568 CTAs, 128 thr.
// Thread = 4 px x 12 ch (24 f32x2 accs, 80 regs -> 6 CTAs/SM, ~24 warps/SM).
// Weights: LDS.64 dup-pair broadcasts (1 wavefront each).
// x: LDG.128 per k, depth-2 rotating prefetch (R6's exact inner loop).
// ---------------------------------------------------------------------------
__global__ __launch_bounds__(128, 6) void kA(
    const float* __restrict__ x, const float* __restrict__ w) {
    __shared__ u64 ws[KQ * 12];             // [k][c] = {w,w}, 5.76 KB
    int tid = threadIdx.x;
    int chb = blockIdx.y * 12;              // channel half base
    int kbase = blockIdx.z * KQ;            // K quarter base
    for (int i = tid; i < KQ * 12; i += 128) {
        int k = i / 12, cc = i % 12;
        float wv = w[(chb + cc) * CIN + kbase + k];
        ws[i] = pk2(wv, wv);
    }
    __syncthreads();

    int p0 = (blockIdx.x * 128 + tid) * 4;  // 4 contiguous px, HW%4==0
    int b = p0 / HW;
    int s = p0 - b * HW;
    const float* xp = x + (size_t)b * CIN * HW + (size_t)kbase * HW + s;

    u64 acc0[12], acc1[12];
#pragma unroll
    for (int c = 0; c < 12; c++) { acc0[c] = 0ull; acc1[c] = 0ull; }

    float4 cur0 = *reinterpret_cast<const float4*>(xp);
    float4 cur1 = *reinterpret_cast<const float4*>(xp + HW);
#pragma unroll 2
    for (int k0 = 0; k0 < KQ; k0 += 2) {
        int kn = (k0 + 2 == KQ) ? 0 : (k0 + 2);   // clamp: redundant L1 hit
        float4 n0 = *reinterpret_cast<const float4*>(xp + (size_t)kn * HW);
        float4 n1 = *reinterpret_cast<const float4*>(xp + (size_t)(kn + 1) * HW);
        {
            u64 xa = pk2(cur0.x, cur0.y);
            u64 xb = pk2(cur0.z, cur0.w);
            const u64* wk = ws + k0 * 12;
#pragma unroll
            for (int c = 0; c < 12; c++) {
                u64 wv = wk[c];
                acc0[c] = fma2(xa, wv, acc0[c]);
                acc1[c] = fma2(xb, wv, acc1[c]);
            }
        }
        {
            u64 xa = pk2(cur1.x, cur1.y);
            u64 xb = pk2(cur1.z, cur1.w);
            const u64* wk = ws + (k0 + 1) * 12;
#pragma unroll
            for (int c = 0; c < 12; c++) {
                u64 wv = wk[c];
                acc0[c] = fma2(xa, wv, acc0[c]);
                acc1[c] = fma2(xb, wv, acc1[c]);
            }
        }
        cur0 = n0; cur1 = n1;
    }
    float* op = g_parts[blockIdx.z] + ((size_t)b * C1 + chb) * HW + s;
#pragma unroll
    for (int c = 0; c < 12; c++) {
        float2 f0 = up2(acc0[c]), f1 = up2(acc1[c]);
        *reinterpret_cast<float4*>(op + (size_t)c * HW) =
            make_float4(f0.x, f0.y, f1.x, f1.y);
    }
}

// ---------------------------------------------------------------------------
// Kernel B: merge 4 partials + BN1, depthwise 3x3 + BN2. One q (4px)/thread.
// Flat grid 2352 x 256. Writes g_s2 (for kC, via L2) and out channels [0,24).
// ---------------------------------------------------------------------------
__global__ __launch_bounds__(256) void kB(
    const float* __restrict__ g1, const float* __restrict__ b1,
    const float* __restrict__ m1, const float* __restrict__ v1,
    const float* __restrict__ wdw,
    const float* __restrict__ g2, const float* __restrict__ b2,
    const float* __restrict__ m2, const float* __restrict__ v2,
    float* __restrict__ out) {
    int idx = blockIdx.x * 256 + threadIdx.x;   // 602112 = 32*24*784
    int q = idx % 784;
    int c = (idx / 784) % C1;
    int b = idx / (784 * C1);
    int h = q / 14;
    int w0 = (q % 14) * 4;
    float iv1 = g1[c] * rsqrtf(v1[c] + EPSV);
    float bi1 = b1[c] - m1[c] * iv1;
    size_t poff = ((size_t)b * C1 + c) * HW;
    const float* p0 = g_p0 + poff;
    const float* p1 = g_p1 + poff;
    const float* p2 = g_p2 + poff;
    const float* p3 = g_p3 + poff;

    float rb[3][6];
#pragma unroll
    for (int dy = 0; dy < 3; dy++) {
        int hh = h + dy - 1;
        bool hok = (hh >= 0) && (hh < HH);
#pragma unroll
        for (int jx = 0; jx < 6; jx++) {
            int ww = w0 + jx - 1;
            int id2 = hh * WWD + ww;
            rb[dy][jx] = (hok && ww >= 0 && ww < WWD)
                ? fmaf((p0[id2] + p1[id2]) + (p2[id2] + p3[id2]), iv1, bi1)
                : 0.0f;
        }
    }
    float wv[9];
#pragma unroll
    for (int t = 0; t < 9; t++) wv[t] = __ldg(wdw + c * 9 + t);
    float acc[4] = {0.f, 0.f, 0.f, 0.f};
#pragma unroll
    for (int dy = 0; dy < 3; dy++)
#pragma unroll
        for (int dx = 0; dx < 3; dx++) {
            float t = wv[dy * 3 + dx];
#pragma unroll
            for (int j = 0; j < 4; j++) acc[j] = fmaf(rb[dy][dx + j], t, acc[j]);
        }
    float iv2 = g2[c] * rsqrtf(v2[c] + EPSV);
    float bi2 = b2[c] - m2[c] * iv2;
    float4 o = make_float4(fmaf(acc[0], iv2, bi2), fmaf(acc[1], iv2, bi2),
                           fmaf(acc[2], iv2, bi2), fmaf(acc[3], iv2, bi2));
    size_t off = poff + h * WWD + w0;
    *reinterpret_cast<float4*>(g_s2 + off) = o;
    size_t ooff = ((size_t)b * OUP + c) * HW + h * WWD + w0;
    *reinterpret_cast<float4*>(out + ooff) = o;
}

// ---------------------------------------------------------------------------
// Kernel C: adder depthwise (24 -> 216) + BN3 + ReLU into out channels [24,240).
// One q (4px) per thread, grid (7, 24, 32) x 128. Reads g_s2 from L2.
// ---------------------------------------------------------------------------
__global__ __launch_bounds__(128) void kC(
    const float* __restrict__ wadd,
    const float* __restrict__ g3, const float* __restrict__ b3,
    const float* __restrict__ m3, const float* __restrict__ v3,
    float* __restrict__ out) {
    int c = blockIdx.y;
    int b = blockIdx.z;
    __shared__ u64 negtap[81];
    __shared__ float sninv[9], sbias[9];
    int tid = threadIdx.x;
    if (tid < 81) {
        float tv = wadd[c * 81 + tid];
        negtap[tid] = pk2(-tv, -tv);
    }
    if (tid < 9) {
        int ch = c * 9 + tid;
        float iv = g3[ch] * rsqrtf(v3[ch] + EPSV);
        sninv[tid] = -iv;
        sbias[tid] = b3[ch] - m3[ch] * iv;
    }
    __syncthreads();
    int q = blockIdx.x * 128 + tid;
    if (q >= 784) return;
    int h = q / 14;
    int w0 = (q % 14) * 4;
    const float* p = g_s2 + ((size_t)b * C1 + c) * HW;

    float rb[3][6];
#pragma unroll
    for (int dy = 0; dy < 3; dy++) {
        int hh = h + dy - 1;
        bool hok = (hh >= 0) && (hh < HH);
#pragma unroll
        for (int jx = 0; jx < 6; jx++) {
            int ww = w0 + jx - 1;
            rb[dy][jx] = (hok && ww >= 0 && ww < WWD) ? p[hh * WWD + ww] : 0.0f;
        }
    }
    u64 nA[9], nB[9];
#pragma unroll
    for (int dy = 0; dy < 3; dy++)
#pragma unroll
        for (int dx = 0; dx < 3; dx++) {
            nA[dy * 3 + dx] = pk2(rb[dy][dx],     rb[dy][dx + 1]);
            nB[dy * 3 + dx] = pk2(rb[dy][dx + 2], rb[dy][dx + 3]);
        }
    size_t obase = ((size_t)b * OUP + C1 + c * 9) * HW + h * WWD + w0;
#pragma unroll
    for (int r = 0; r < 9; r++) {
        u64 aA = 0ull, aB = 0ull;
#pragma unroll
        for (int t = 0; t < 9; t++) {
            u64 nt = negtap[r * 9 + t];
            u64 dA = add2(nA[t], nt) & 0x7FFFFFFF7FFFFFFFull;
            u64 dB = add2(nB[t], nt) & 0x7FFFFFFF7FFFFFFFull;
            aA = add2(aA, dA);
            aB = add2(aB, dB);
        }
        float2 fa = up2(aA), fb = up2(aB);
        float ni = sninv[r], bi = sbias[r];
        float4 o = make_float4(fmaxf(fmaf(fa.x, ni, bi), 0.f),
                               fmaxf(fmaf(fa.y, ni, bi), 0.f),
                               fmaxf(fmaf(fb.x, ni, bi), 0.f),
                               fmaxf(fmaf(fb.y, ni, bi), 0.f));
        *reinterpret_cast<float4*>(out + obase + (size_t)r * HW) = o;
    }
}

extern "C" void kernel_launch(void* const* d_in, const int* in_sizes, int n_in,
                              void* d_out, int out_size) {
    const float* x   = (const float*)d_in[0];
    const float* wp  = (const float*)d_in[1];
    const float* g1  = (const float*)d_in[2];
    const float* b1  = (const float*)d_in[3];
    const float* m1  = (const float*)d_in[4];
    const float* v1  = (const float*)d_in[5];
    const float* wdw = (const float*)d_in[6];
    const float* g2  = (const float*)d_in[7];
    const float* b2  = (const float*)d_in[8];
    const float* m2  = (const float*)d_in[9];
    const float* v2  = (const float*)d_in[10];
    const float* wa  = (const float*)d_in[11];
    const float* g3  = (const float*)d_in[12];
    const float* b3  = (const float*)d_in[13];
    const float* m3  = (const float*)d_in[14];
    const float* v3  = (const float*)d_in[15];
    float* out = (float*)d_out;

    kA<<<dim3(196, 2, 4), 128>>>(x, wp);
    kB<<<2352, 256>>>(g1, b1, m1, v1, wdw, g2, b2, m2, v2, out);
    kC<<<dim3(7, 24, 32), 128>>>(wa, g3, b3, m3, v3, out);
}

// round 13
// speedup vs baseline: 1.3219x; 1.1383x over previous
#include <cuda_runtime.h>
#include <cstdint>

#define EPSV 1e-5f
constexpr int BB = 32, CIN = 240, C1 = 24, HH = 56, WWD = 56, HW = 3136;
constexpr int OUP = 240;
constexpr int KQ = 60;                 // K quarter size

// Scratch — __device__ globals per allocation rules.
__device__ float g_p0[BB * C1 * HW];
__device__ float g_p1[BB * C1 * HW];
__device__ float g_p2[BB * C1 * HW];
__device__ float g_p3[BB * C1 * HW];
__device__ float g_s2[BB * C1 * HW];   // after dw3x3 + bn2 (== x1)
__device__ float* const g_parts[4] = {g_p0, g_p1, g_p2, g_p3};

using u64 = unsigned long long;

__device__ __forceinline__ u64 pk2(float lo, float hi) {
    u64 r; asm("mov.b64 %0, {%1,%2};" : "=l"(r) : "f"(lo), "f"(hi)); return r;
}
__device__ __forceinline__ float2 up2(u64 v) {
    float2 f; asm("mov.b64 {%0,%1}, %2;" : "=f"(f.x), "=f"(f.y) : "l"(v)); return f;
}
__device__ __forceinline__ u64 fma2(u64 a, u64 b, u64 c) {
    u64 d; asm("fma.rn.f32x2 %0, %1, %2, %3;" : "=l"(d) : "l"(a), "l"(b), "l"(c)); return d;
}
__device__ __forceinline__ u64 add2(u64 a, u64 b) {
    u64 d; asm("add.rn.f32x2 %0, %1, %2;" : "=l"(d) : "l"(a), "l"(b)); return d;
}

// ---------------------------------------------------------------------------
// Kernel A: unchanged from R12 (best measured: 46.3us).
// grid (196 px-tiles, 2 ch-halves, 4 K-quarters) = 1568 CTAs, 128 thr.
// ---------------------------------------------------------------------------
__global__ __launch_bounds__(128, 6) void kA(
    const float* __restrict__ x, const float* __restrict__ w) {
    __shared__ u64 ws[KQ * 12];             // [k][c] = {w,w}, 5.76 KB
    int tid = threadIdx.x;
    int chb = blockIdx.y * 12;              // channel half base
    int kbase = blockIdx.z * KQ;            // K quarter base
    for (int i = tid; i < KQ * 12; i += 128) {
        int k = i / 12, cc = i % 12;
        float wv = w[(chb + cc) * CIN + kbase + k];
        ws[i] = pk2(wv, wv);
    }
    __syncthreads();

    int p0 = (blockIdx.x * 128 + tid) * 4;  // 4 contiguous px, HW%4==0
    int b = p0 / HW;
    int s = p0 - b * HW;
    const float* xp = x + (size_t)b * CIN * HW + (size_t)kbase * HW + s;

    u64 acc0[12], acc1[12];
#pragma unroll
    for (int c = 0; c < 12; c++) { acc0[c] = 0ull; acc1[c] = 0ull; }

    float4 cur0 = *reinterpret_cast<const float4*>(xp);
    float4 cur1 = *reinterpret_cast<const float4*>(xp + HW);
#pragma unroll 2
    for (int k0 = 0; k0 < KQ; k0 += 2) {
        int kn = (k0 + 2 == KQ) ? 0 : (k0 + 2);   // clamp: redundant L1 hit
        float4 n0 = *reinterpret_cast<const float4*>(xp + (size_t)kn * HW);
        float4 n1 = *reinterpret_cast<const float4*>(xp + (size_t)(kn + 1) * HW);
        {
            u64 xa = pk2(cur0.x, cur0.y);
            u64 xb = pk2(cur0.z, cur0.w);
            const u64* wk = ws + k0 * 12;
#pragma unroll
            for (int c = 0; c < 12; c++) {
                u64 wv = wk[c];
                acc0[c] = fma2(xa, wv, acc0[c]);
                acc1[c] = fma2(xb, wv, acc1[c]);
            }
        }
        {
            u64 xa = pk2(cur1.x, cur1.y);
            u64 xb = pk2(cur1.z, cur1.w);
            const u64* wk = ws + (k0 + 1) * 12;
#pragma unroll
            for (int c = 0; c < 12; c++) {
                u64 wv = wk[c];
                acc0[c] = fma2(xa, wv, acc0[c]);
                acc1[c] = fma2(xb, wv, acc1[c]);
            }
        }
        cur0 = n0; cur1 = n1;
    }
    float* op = g_parts[blockIdx.z] + ((size_t)b * C1 + chb) * HW + s;
#pragma unroll
    for (int c = 0; c < 12; c++) {
        float2 f0 = up2(acc0[c]), f1 = up2(acc1[c]);
        *reinterpret_cast<float4*>(op + (size_t)c * HW) =
            make_float4(f0.x, f0.y, f1.x, f1.y);
    }
}

// ---------------------------------------------------------------------------
// Kernel B: one block per (b,c) plane (768 blocks x 256 thr).
// Stage 1: float4-vectorized merge of 4 partials + BN1 -> shared plane tile
//   (12 LDG.128/thread vs 72 scalar LDG in R12's kB).
// Stage 2: dw3x3 + BN2 with halos from SHARED -> g_s2 + out[:, :24).
// ---------------------------------------------------------------------------
__global__ __launch_bounds__(256) void kB(
    const float* __restrict__ g1, const float* __restrict__ b1,
    const float* __restrict__ m1, const float* __restrict__ v1,
    const float* __restrict__ wdw,
    const float* __restrict__ g2, const float* __restrict__ b2,
    const float* __restrict__ m2, const float* __restrict__ v2,
    float* __restrict__ out) {
    __shared__ float tile[HW];             // 12544 B merged+bn1 plane
    int c = blockIdx.x % C1;
    int b = blockIdx.x / C1;
    int tid = threadIdx.x;
    float iv1 = g1[c] * rsqrtf(v1[c] + EPSV);
    float bi1 = b1[c] - m1[c] * iv1;
    size_t poff = ((size_t)b * C1 + c) * HW;
    const float4* p0 = reinterpret_cast<const float4*>(g_p0 + poff);
    const float4* p1 = reinterpret_cast<const float4*>(g_p1 + poff);
    const float4* p2 = reinterpret_cast<const float4*>(g_p2 + poff);
    const float4* p3 = reinterpret_cast<const float4*>(g_p3 + poff);

    // Stage 1: merge + BN1 into shared (784 float4 slots)
#pragma unroll 1
    for (int i = tid; i < 784; i += 256) {
        float4 a = p0[i], q1 = p1[i], q2 = p2[i], q3 = p3[i];
        float4 o;
        o.x = fmaf((a.x + q1.x) + (q2.x + q3.x), iv1, bi1);
        o.y = fmaf((a.y + q1.y) + (q2.y + q3.y), iv1, bi1);
        o.z = fmaf((a.z + q1.z) + (q2.z + q3.z), iv1, bi1);
        o.w = fmaf((a.w + q1.w) + (q2.w + q3.w), iv1, bi1);
        *reinterpret_cast<float4*>(tile + i * 4) = o;
    }
    __syncthreads();

    // Stage 2: dw3x3 + BN2 from shared
    float wv[9];
#pragma unroll
    for (int t = 0; t < 9; t++) wv[t] = __ldg(wdw + c * 9 + t);
    float iv2 = g2[c] * rsqrtf(v2[c] + EPSV);
    float bi2 = b2[c] - m2[c] * iv2;
    float* outc = out + ((size_t)b * OUP + c) * HW;
    float* s2c = g_s2 + poff;

#pragma unroll 1
    for (int q = tid; q < 784; q += 256) {
        int h = q / 14;
        int w0 = (q % 14) * 4;
        float rb[3][6];
#pragma unroll
        for (int dy = 0; dy < 3; dy++) {
            int hh = h + dy - 1;
            bool hok = (hh >= 0) && (hh < HH);
#pragma unroll
            for (int jx = 0; jx < 6; jx++) {
                int ww = w0 + jx - 1;
                rb[dy][jx] = (hok && ww >= 0 && ww < WWD)
                               ? tile[hh * WWD + ww] : 0.0f;
            }
        }
        float acc[4] = {0.f, 0.f, 0.f, 0.f};
#pragma unroll
        for (int dy = 0; dy < 3; dy++)
#pragma unroll
            for (int dx = 0; dx < 3; dx++) {
                float t = wv[dy * 3 + dx];
#pragma unroll
                for (int j = 0; j < 4; j++)
                    acc[j] = fmaf(rb[dy][dx + j], t, acc[j]);
            }
        float4 o = make_float4(fmaf(acc[0], iv2, bi2), fmaf(acc[1], iv2, bi2),
                               fmaf(acc[2], iv2, bi2), fmaf(acc[3], iv2, bi2));
        *reinterpret_cast<float4*>(s2c + h * WWD + w0) = o;
        *reinterpret_cast<float4*>(outc + h * WWD + w0) = o;
    }
}

// ---------------------------------------------------------------------------
// Kernel C: adder depthwise (24 -> 216) + BN3 + ReLU into out channels [24,240).
// One q (4px) per thread, grid (7, 24, 32) x 128. Reads g_s2 from L2.
// ---------------------------------------------------------------------------
__global__ __launch_bounds__(128) void kC(
    const float* __restrict__ wadd,
    const float* __restrict__ g3, const float* __restrict__ b3,
    const float* __restrict__ m3, const float* __restrict__ v3,
    float* __restrict__ out) {
    int c = blockIdx.y;
    int b = blockIdx.z;
    __shared__ u64 negtap[81];
    __shared__ float sninv[9], sbias[9];
    int tid = threadIdx.x;
    if (tid < 81) {
        float tv = wadd[c * 81 + tid];
        negtap[tid] = pk2(-tv, -tv);
    }
    if (tid < 9) {
        int ch = c * 9 + tid;
        float iv = g3[ch] * rsqrtf(v3[ch] + EPSV);
        sninv[tid] = -iv;
        sbias[tid] = b3[ch] - m3[ch] * iv;
    }
    __syncthreads();
    int q = blockIdx.x * 128 + tid;
    if (q >= 784) return;
    int h = q / 14;
    int w0 = (q % 14) * 4;
    const float* p = g_s2 + ((size_t)b * C1 + c) * HW;

    float rb[3][6];
#pragma unroll
    for (int dy = 0; dy < 3; dy++) {
        int hh = h + dy - 1;
        bool hok = (hh >= 0) && (hh < HH);
#pragma unroll
        for (int jx = 0; jx < 6; jx++) {
            int ww = w0 + jx - 1;
            rb[dy][jx] = (hok && ww >= 0 && ww < WWD) ? p[hh * WWD + ww] : 0.0f;
        }
    }
    u64 nA[9], nB[9];
#pragma unroll
    for (int dy = 0; dy < 3; dy++)
#pragma unroll
        for (int dx = 0; dx < 3; dx++) {
            nA[dy * 3 + dx] = pk2(rb[dy][dx],     rb[dy][dx + 1]);
            nB[dy * 3 + dx] = pk2(rb[dy][dx + 2], rb[dy][dx + 3]);
        }
    size_t obase = ((size_t)b * OUP + C1 + c * 9) * HW + h * WWD + w0;
#pragma unroll
    for (int r = 0; r < 9; r++) {
        u64 aA = 0ull, aB = 0ull;
#pragma unroll
        for (int t = 0; t < 9; t++) {
            u64 nt = negtap[r * 9 + t];
            u64 dA = add2(nA[t], nt) & 0x7FFFFFFF7FFFFFFFull;
            u64 dB = add2(nB[t], nt) & 0x7FFFFFFF7FFFFFFFull;
            aA = add2(aA, dA);
            aB = add2(aB, dB);
        }
        float2 fa = up2(aA), fb = up2(aB);
        float ni = sninv[r], bi = sbias[r];
        float4 o = make_float4(fmaxf(fmaf(fa.x, ni, bi), 0.f),
                               fmaxf(fmaf(fa.y, ni, bi), 0.f),
                               fmaxf(fmaf(fb.x, ni, bi), 0.f),
                               fmaxf(fmaf(fb.y, ni, bi), 0.f));
        *reinterpret_cast<float4*>(out + obase + (size_t)r * HW) = o;
    }
}

extern "C" void kernel_launch(void* const* d_in, const int* in_sizes, int n_in,
                              void* d_out, int out_size) {
    const float* x   = (const float*)d_in[0];
    const float* wp  = (const float*)d_in[1];
    const float* g1  = (const float*)d_in[2];
    const float* b1  = (const float*)d_in[3];
    const float* m1  = (const float*)d_in[4];
    const float* v1  = (const float*)d_in[5];
    const float* wdw = (const float*)d_in[6];
    const float* g2  = (const float*)d_in[7];
    const float* b2  = (const float*)d_in[8];
    const float* m2  = (const float*)d_in[9];
    const float* v2  = (const float*)d_in[10];
    const float* wa  = (const float*)d_in[11];
    const float* g3  = (const float*)d_in[12];
    const float* b3  = (const float*)d_in[13];
    const float* m3  = (const float*)d_in[14];
    const float* v3  = (const float*)d_in[15];
    float* out = (float*)d_out;

    kA<<<dim3(196, 2, 4), 128>>>(x, wp);
    kB<<<BB * C1, 256>>>(g1, b1, m1, v1, wdw, g2, b2, m2, v2, out);
    kC<<<dim3(7, 24, 32), 128>>>(wa, g3, b3, m3, v3, out);
}